// round 12
// baseline (speedup 1.0000x reference)
#include <cuda_runtime.h>

#define Bq 8
#define Nq 8192
#define Cq 128
#define Mq 2048
#define Kq 32

typedef unsigned long long u64p;

// device-global scratch (allocation-free)
__device__ ulonglong2 g_pA[Bq * (Nq / 2)];   // packed {x01, y01} per pair
__device__ ulonglong2 g_pB[Bq * (Nq / 2)];   // packed {z01, p2_01} per pair
__device__ unsigned   g_prog[Bq];            // FPS progress counters

// ---- packed f32x2 helpers (per-lane rounding identical to scalar RN ops) ----
#define PK2(d, lo, hi)                                                      \
    asm("mov.b64 %0, {%1, %2};" : "=l"(d)                                   \
        : "r"(__float_as_uint(lo)), "r"(__float_as_uint(hi)))
#define UPK2(lo, hi, s)                                                     \
    do { unsigned _a, _b;                                                   \
         asm("mov.b64 {%0, %1}, %2;" : "=r"(_a), "=r"(_b) : "l"(s));        \
         (lo) = __uint_as_float(_a); (hi) = __uint_as_float(_b); } while (0)
#define ADD2(d, a, b) asm("add.rn.f32x2 %0, %1, %2;" : "=l"(d) : "l"(a), "l"(b))
#define MUL2(d, a, b) asm("mul.rn.f32x2 %0, %1, %2;" : "=l"(d) : "l"(a), "l"(b))
#define FMA2(d, a, b, c)                                                    \
    asm("fma.rn.f32x2 %0, %1, %2, %3;" : "=l"(d) : "l"(a), "l"(b), "l"(c))

__device__ __forceinline__ unsigned redux_max_u32(unsigned v) {
    unsigned r;
    asm("redux.sync.max.u32 %0, %1, 0xffffffff;" : "=r"(r) : "r"(v));
    return r;
}
__device__ __forceinline__ unsigned redux_min_u32(unsigned v) {
    unsigned r;
    asm("redux.sync.min.u32 %0, %1, 0xffffffff;" : "=r"(r) : "r"(v));
    return r;
}

// ---------------------------------------------------------------------------
// pack kernel: SoA pair-packed coords + |p|^2 (bit-exact p2 path), and
// resets the progress counters (needed on every graph replay).
// ---------------------------------------------------------------------------
__global__ void __launch_bounds__(512, 1) pack_kernel(
    const float* __restrict__ coords)
{
    const int b   = blockIdx.x;
    const int tid = threadIdx.x;
    if (tid == 0) g_prog[b] = 0u;
    const float* cb = coords + (size_t)b * Nq * 3;
    for (int jp = tid; jp < Nq / 2; jp += 512) {
        const int j0 = 2 * jp, j1 = j0 + 1;
        const float x0 = cb[3 * j0], y0 = cb[3 * j0 + 1], z0 = cb[3 * j0 + 2];
        const float x1 = cb[3 * j1], y1 = cb[3 * j1 + 1], z1 = cb[3 * j1 + 2];
        const float p20 = __fadd_rn(
            __fadd_rn(__fmul_rn(x0, x0), __fmul_rn(y0, y0)), __fmul_rn(z0, z0));
        const float p21 = __fadd_rn(
            __fadd_rn(__fmul_rn(x1, x1), __fmul_rn(y1, y1)), __fmul_rn(z1, z1));
        ulonglong2 A, B;
        PK2(A.x, x0, x1); PK2(A.y, y0, y1);
        PK2(B.x, z0, z1); PK2(B.y, p20, p21);
        g_pA[b * (Nq / 2) + jp] = A;
        g_pB[b * (Nq / 2) + jp] = B;
    }
}

// ---------------------------------------------------------------------------
// Fused kernel, cluster dims (2,1,1).
//   blocks 0..15  : FPS, one 2-CTA cluster per batch (rank r owns 4096 pts).
//   blocks 16..143: kNN consumers (verbatim R11 structure, offset +16).
// Consumer clusters never execute cluster ops (legal; nobody waits).
// 144 CTAs co-resident (1/SM) -> spin-waits cannot deadlock.
// ---------------------------------------------------------------------------
#define HSTRIDE 512     // heap column stride (one column per thread)

// hygienic heap insert (reserved _hs_* names; see R8 shadowing post-mortem)
#define HEAP_SIFT(KEY)                                                      \
    {                                                                       \
        const u64p _hs_k = (KEY);                                           \
        u64p _hs_lc = hp[1 * HSTRIDE + tid];                                \
        u64p _hs_rc = hp[2 * HSTRIDE + tid];                                \
        u64p _hs_mc = (_hs_rc > _hs_lc) ? _hs_rc : _hs_lc;                  \
        if (_hs_mc > _hs_k) {                                               \
            hp[0 * HSTRIDE + tid] = _hs_mc;                                 \
            root = _hs_mc;                                                  \
            int _hs_i = (_hs_rc > _hs_lc) ? 2 : 1;                          \
            _Pragma("unroll")                                               \
            for (int _hs_lvl = 1; _hs_lvl < 5; ++_hs_lvl) {                 \
                const int _hs_cn = 2 * _hs_i + 1;                           \
                if (_hs_cn > 31) break;                                     \
                _hs_lc = hp[_hs_cn * HSTRIDE + tid];                        \
                _hs_rc = hp[(_hs_cn + 1) * HSTRIDE + tid];                  \
                _hs_mc = (_hs_rc > _hs_lc) ? _hs_rc : _hs_lc;               \
                if (_hs_mc <= _hs_k) break;                                 \
                hp[_hs_i * HSTRIDE + tid] = _hs_mc;                         \
                _hs_i = (_hs_rc > _hs_lc) ? (_hs_cn + 1) : _hs_cn;          \
            }                                                               \
            hp[_hs_i * HSTRIDE + tid] = _hs_k;                              \
        } else {                                                            \
            hp[0 * HSTRIDE + tid] = _hs_k;                                  \
            root = _hs_k;                                                   \
        }                                                                   \
    }
#define ROOTF_UPDATE()                                                      \
    {                                                                       \
        const unsigned _ru_hi = (unsigned)(root >> 32);                     \
        const unsigned _ru_fb =                                             \
            _ru_hi ^ ((_ru_hi & 0x80000000u) ? 0x80000000u : 0xFFFFFFFFu);  \
        root_f = __uint_as_float(_ru_fb);                                   \
    }
#define MONO(bits) ((bits) ^ ((unsigned)((int)(bits) >> 31) | 0x80000000u))

__global__ void __launch_bounds__(512, 1) __cluster_dims__(2, 1, 1)
fused_kernel(
    const float* __restrict__ coords, const float* __restrict__ feats,
    float* __restrict__ out_coords, float* __restrict__ out_feats)
{
    extern __shared__ char smraw[];
    const int tid = threadIdx.x;

    if (blockIdx.x < 2 * Bq) {
        // ============================ FPS role =============================
        float4* sp    = (float4*)smraw;             // full 8192 pts = 128 KB
        u64p*   k_all = (u64p*)(smraw + 131072);    // [2 parity][32 warpkeys]

        const int b = blockIdx.x >> 1;
        unsigned r;                                  // cluster rank 0/1
        asm("mov.u32 %0, %%cluster_ctarank;" : "=r"(r));
        const int w = tid >> 5, lane = tid & 31;
        const float* cb = coords + (size_t)b * Nq * 3;

        for (int j = tid; j < Nq; j += 512)
            sp[j] = make_float4(cb[3 * j], cb[3 * j + 1], cb[3 * j + 2], 0.0f);
        __syncthreads();

        // peer address of k_all (same offset in peer CTA's smem)
        unsigned k_all_local = (unsigned)__cvta_generic_to_shared(k_all);
        unsigned k_all_peer;
        asm("mapa.shared::cluster.u32 %0, %1, %2;"
            : "=r"(k_all_peer) : "r"(k_all_local), "r"(r ^ 1u));

        // pack this rank's 8 points/thread (4 pairs) into registers
        const int base = (int)r * (Nq / 2);
        u64p px[4], py[4], pz[4];
        float dist[8];
#pragma unroll
        for (int k = 0; k < 4; ++k) {
            const float4 a = sp[base + (2 * k) * 512 + tid];
            const float4 c = sp[base + (2 * k + 1) * 512 + tid];
            PK2(px[k], a.x, c.x);
            PK2(py[k], a.y, c.y);
            PK2(pz[k], a.z, c.z);
            dist[2 * k] = 3.0e38f; dist[2 * k + 1] = 3.0e38f;
        }

        int cur = 0;
        float* ob = out_coords + (size_t)b * Mq * 3;

        for (int step = 0; step < Mq; ++step) {
            const int p = step & 1;
            const float4 c = sp[cur];
            if (r == 0 && tid == 0) {
                ob[3 * step + 0] = c.x;
                ob[3 * step + 1] = c.y;
                ob[3 * step + 2] = c.z;
                if ((step & 63) == 63) {  // steps 0..step now final
                    asm volatile("st.release.gpu.global.u32 [%0], %1;"
                                 :: "l"(&g_prog[b]), "r"((unsigned)(step + 1))
                                 : "memory");
                }
            }
            u64p ncx, ncy, ncz;
            PK2(ncx, -c.x, -c.x);
            PK2(ncy, -c.y, -c.y);
            PK2(ncz, -c.z, -c.z);

#pragma unroll
            for (int k = 0; k < 4; ++k) {
                u64p dx, dy, dz, xx, yy, zz, ss, dd;
                ADD2(dx, px[k], ncx);
                ADD2(dy, py[k], ncy);
                ADD2(dz, pz[k], ncz);
                MUL2(xx, dx, dx);
                MUL2(yy, dy, dy);
                MUL2(zz, dz, dz);
                ADD2(ss, xx, yy);
                ADD2(dd, ss, zz);
                float d0, d1; UPK2(d0, d1, dd);
                dist[2 * k]     = fminf(dist[2 * k], d0);
                dist[2 * k + 1] = fminf(dist[2 * k + 1], d1);
            }
            // per-thread max (tree over 8)
            float bv = dist[0];
#pragma unroll
            for (int i = 1; i < 8; ++i) bv = fmaxf(bv, dist[i]);

            // warp value max first (latency shadows the slot scan)
            const unsigned bb = __float_as_uint(bv);
            const unsigned wm = redux_max_u32(bb);

            // lowest matching slot (pair test + min tree) -> global index
            int ck[4];
#pragma unroll
            for (int k = 0; k < 4; ++k)
                ck[k] = (dist[2 * k] == bv) ? (2 * k)
                        : ((dist[2 * k + 1] == bv) ? (2 * k + 1) : 8);
            ck[0] = min(ck[0], ck[1]);
            ck[2] = min(ck[2], ck[3]);
            ck[0] = min(ck[0], ck[2]);
            const int bi = base + ck[0] * 512 + tid;   // global point index

            const unsigned wbi =
                redux_min_u32((bb == wm) ? (unsigned)bi : 0x7fffffffu);
            if (lane == 0) {
                // key: max value, then min index (stored inverted)
                const u64p key = ((u64p)wm << 32) |
                                 (u64p)(0xFFFFFFFFu ^ wbi);
                const unsigned slot_off =
                    (unsigned)((p * 32 + (int)r * 16 + w) * 8);
                // local copy
                asm volatile("st.shared.b64 [%0], %1;"
                             :: "r"(k_all_local + slot_off), "l"(key)
                             : "memory");
                // peer copy (same slot index in peer's k_all)
                asm volatile("st.shared::cluster.b64 [%0], %1;"
                             :: "r"(k_all_peer + slot_off), "l"(key)
                             : "memory");
            }
            // ONE barrier: cluster-wide (superset of block sync; release
            // /acquire orders the k_all stores for both CTAs)
            asm volatile("barrier.cluster.arrive.aligned;" ::: "memory");
            asm volatile("barrier.cluster.wait.aligned;" ::: "memory");

            // stage2: 32 warp-keys (both CTAs), every warp redundantly
            const u64p kk = k_all[p * 32 + lane];
            const unsigned hi = (unsigned)(kk >> 32);
            const unsigned lo = (unsigned)kk;
            const unsigned mh = redux_max_u32(hi);
            const unsigned ml = redux_max_u32((hi == mh) ? lo : 0u);
            cur = (int)(0xFFFFFFFFu ^ ml);
        }
        if (r == 0 && tid == 0)
            asm volatile("st.release.gpu.global.u32 [%0], %1;"
                         :: "l"(&g_prog[b]), "r"((unsigned)Mq) : "memory");
        return;
    }

    // ======================= kNN + aggregation role =======================
    // CTA handles two 64-center blocks of batch b: blk = xb and xb+16.
    u64p* hp = (u64p*)smraw;               // 33 x 512 u64 = 132 KB
    const int cta = blockIdx.x - 2 * Bq;
    const int b   = cta & 7;               // batch
    const int xb  = cta >> 3;              // 0..15
    const int t   = tid & 63;              // center slot (0..63)
    const int g   = tid >> 6;              // point split (0..7)

    const u64p INIT_KEY = 0xFF800000FFFFFFFFull;
    const ulonglong2* pA = g_pA + (size_t)b * (Nq / 2);
    const ulonglong2* pB = g_pB + (size_t)b * (Nq / 2);

#pragma unroll 1
    for (int item = 0; item < 2; ++item) {
        const int blk = xb + item * 16;    // 64-center block (0..31)
        __syncthreads();                   // prev item's agg reads done

        // heap init: 32 real nodes -> +inf keys; slot 32 = 0-sentinel
#pragma unroll
        for (int n = 0; n < 32; ++n) hp[n * HSTRIDE + tid] = INIT_KEY;
        hp[32 * HSTRIDE + tid] = 0ull;
        __syncthreads();

        // wait for FPS progress (centers [0, (blk+1)*64) final)
        const unsigned need = (unsigned)((blk + 1) * 64);
        if (tid == 0) {
            unsigned v;
            do {
                asm volatile("ld.acquire.gpu.global.u32 %0, [%1];"
                             : "=r"(v) : "l"(&g_prog[b]) : "memory");
                if (v >= need) break;
                __nanosleep(256);
            } while (true);
        }
        __syncthreads();
        {   // per-thread acquire (counter monotone -> sees >= need)
            unsigned v;
            asm volatile("ld.acquire.gpu.global.u32 %0, [%1];"
                         : "=r"(v) : "l"(&g_prog[b]) : "memory");
            (void)v;
        }

        const int m = blk * 64 + t;        // center index within batch
        const float* cc = out_coords + ((size_t)b * Mq + m) * 3;
        const float cx = cc[0], cy = cc[1], cz = cc[2];
        const float c2 = __fadd_rn(
            __fadd_rn(__fmul_rn(cx, cx), __fmul_rn(cy, cy)),
            __fmul_rn(cz, cz));
        u64p vcx, vcy, vcz, vc2, vn2, vz0;
        PK2(vcx, cx, cx); PK2(vcy, cy, cy); PK2(vcz, cz, cz);
        PK2(vc2, c2, c2); PK2(vn2, -2.0f, -2.0f); PK2(vz0, 0.0f, 0.0f);

        u64p  root   = INIT_KEY;
        float root_f = __uint_as_float(0x7F800000u);   // +inf

        // scan this 1/8 split of the points (bit-exact distance math)
        const int jp0 = g * (Nq / 16), jp1 = jp0 + (Nq / 16);
#pragma unroll 4
        for (int jp = jp0; jp < jp1; ++jp) {
            const ulonglong2 A = pA[jp];
            const ulonglong2 B = pB[jp];
            u64p tt, dotv, s2, d2v;
            MUL2(tt, A.x, vcx);
            FMA2(tt, A.y, vcy, tt);
            FMA2(dotv, B.x, vcz, tt);
            ADD2(s2, vc2, B.y);
            FMA2(d2v, dotv, vn2, s2);
            ADD2(d2v, d2v, vz0);       // -0 -> +0 (value otherwise exact)
            float d0, d1; UPK2(d0, d1, d2v);
            if (d0 < root_f) {
                u64p k0; const unsigned m0 = MONO(__float_as_uint(d0));
                asm("mov.b64 %0, {%1, %2};" : "=l"(k0)
                    : "r"((unsigned)(2 * jp)), "r"(m0));
                HEAP_SIFT(k0) ROOTF_UPDATE()
            }
            if (d1 < root_f) {
                u64p k1; const unsigned m1 = MONO(__float_as_uint(d1));
                asm("mov.b64 %0, {%1, %2};" : "=l"(k1)
                    : "r"((unsigned)(2 * jp + 1)), "r"(m1));
                HEAP_SIFT(k1) ROOTF_UPDATE()
            }
        }
        __syncthreads();

        // merge: thread t (<64) folds the 7 foreign partial heaps into its
        // own column. u64 key order == (value, index) stable top_k rule.
        if (tid < 64) {
#pragma unroll
            for (int g2 = 1; g2 < 8; ++g2) {
                const int col = t + 64 * g2;
#pragma unroll
                for (int n = 0; n < 32; ++n) {
                    const u64p fkey = hp[n * HSTRIDE + col];
                    if (fkey < root) HEAP_SIFT(fkey)
                }
            }
        }
        __syncthreads();

        // fused aggregation: warp w handles centers w*4..w*4+3; lane =
        // channel quad. Indices from heap low words (ascending slots).
        const int w = tid >> 5, lane = tid & 31;
        const unsigned* hlo = (const unsigned*)hp;
        const float4* fb4 = (const float4*)(feats + (size_t)b * Nq * Cq);
#pragma unroll
        for (int c4 = 0; c4 < 4; ++c4) {
            const int c  = w * 4 + c4;         // center slot 0..63
            const int mm = blk * 64 + c;
            float ax = 0.f, ay = 0.f, az = 0.f, aw = 0.f;
#pragma unroll
            for (int s = 0; s < Kq; ++s) {
                const unsigned idx = hlo[(s * HSTRIDE + c) * 2];
                const float4 v = fb4[(size_t)idx * 32 + lane];
                ax += v.x; ay += v.y; az += v.z; aw += v.w;
            }
            float4 r;
            r.x = ax * 0.03125f; r.y = ay * 0.03125f;
            r.z = az * 0.03125f; r.w = aw * 0.03125f;
            ((float4*)out_feats)[((size_t)b * Mq + mm) * 32 + lane] = r;
        }
    }
}

// ---------------------------------------------------------------------------
extern "C" void kernel_launch(void* const* d_in, const int* in_sizes, int n_in,
                              void* d_out, int out_size)
{
    const float* coords = (const float*)d_in[0];  // (8, 8192, 3) f32
    const float* feats  = (const float*)d_in[1];  // (8, 8192, 128) f32
    float* out        = (float*)d_out;
    float* out_coords = out;                       // (8, 2048, 3)
    float* out_feats  = out + (size_t)Bq * Mq * 3; // (8, 2048, 128)

    const int fused_smem = 33 * HSTRIDE * 8;       // 135,168 B (>= 128K+512)

    cudaFuncSetAttribute(fused_kernel, cudaFuncAttributeMaxDynamicSharedMemorySize,
                         fused_smem);

    pack_kernel<<<Bq, 512>>>(coords);
    // 16 FPS CTAs (8 clusters of 2) + 128 consumers = 144 (divisible by 2)
    fused_kernel<<<2 * Bq + Bq * 16, 512, fused_smem>>>(coords, feats,
                                                        out_coords, out_feats);
}

// round 13
// speedup vs baseline: 1.2184x; 1.2184x over previous
#include <cuda_runtime.h>

#define Bq 8
#define Nq 8192
#define Cq 128
#define Mq 2048
#define Kq 32

typedef unsigned long long u64p;

// device-global scratch (allocation-free)
__device__ ulonglong2 g_pA[Bq * (Nq / 2)];   // packed {x01, y01} per pair
__device__ ulonglong2 g_pB[Bq * (Nq / 2)];   // packed {z01, p2_01} per pair
__device__ unsigned   g_prog[Bq];            // FPS progress counters

// ---- packed f32x2 helpers (per-lane rounding identical to scalar RN ops) ----
#define PK2(d, lo, hi)                                                      \
    asm("mov.b64 %0, {%1, %2};" : "=l"(d)                                   \
        : "r"(__float_as_uint(lo)), "r"(__float_as_uint(hi)))
#define UPK2(lo, hi, s)                                                     \
    do { unsigned _a, _b;                                                   \
         asm("mov.b64 {%0, %1}, %2;" : "=r"(_a), "=r"(_b) : "l"(s));        \
         (lo) = __uint_as_float(_a); (hi) = __uint_as_float(_b); } while (0)
#define ADD2(d, a, b) asm("add.rn.f32x2 %0, %1, %2;" : "=l"(d) : "l"(a), "l"(b))
#define MUL2(d, a, b) asm("mul.rn.f32x2 %0, %1, %2;" : "=l"(d) : "l"(a), "l"(b))
#define FMA2(d, a, b, c)                                                    \
    asm("fma.rn.f32x2 %0, %1, %2, %3;" : "=l"(d) : "l"(a), "l"(b), "l"(c))

__device__ __forceinline__ unsigned redux_max_u32(unsigned v) {
    unsigned r;
    asm("redux.sync.max.u32 %0, %1, 0xffffffff;" : "=r"(r) : "r"(v));
    return r;
}
__device__ __forceinline__ unsigned redux_min_u32(unsigned v) {
    unsigned r;
    asm("redux.sync.min.u32 %0, %1, 0xffffffff;" : "=r"(r) : "r"(v));
    return r;
}

// ---------------------------------------------------------------------------
// pack kernel: SoA pair-packed coords + |p|^2 (bit-exact p2 path), and
// resets the progress counters (needed on every graph replay).
// 64 CTAs (8 slices per batch), one-shot: ~2us.
// ---------------------------------------------------------------------------
__global__ void __launch_bounds__(512, 1) pack_kernel(
    const float* __restrict__ coords)
{
    const int b   = blockIdx.x >> 3;
    const int s   = blockIdx.x & 7;
    const int tid = threadIdx.x;
    if (s == 0 && tid == 0) g_prog[b] = 0u;
    const float* cb = coords + (size_t)b * Nq * 3;
    const int jp = s * 512 + tid;              // 8 x 512 = 4096 pairs
    {
        const int j0 = 2 * jp, j1 = j0 + 1;
        const float x0 = cb[3 * j0], y0 = cb[3 * j0 + 1], z0 = cb[3 * j0 + 2];
        const float x1 = cb[3 * j1], y1 = cb[3 * j1 + 1], z1 = cb[3 * j1 + 2];
        const float p20 = __fadd_rn(
            __fadd_rn(__fmul_rn(x0, x0), __fmul_rn(y0, y0)), __fmul_rn(z0, z0));
        const float p21 = __fadd_rn(
            __fadd_rn(__fmul_rn(x1, x1), __fmul_rn(y1, y1)), __fmul_rn(z1, z1));
        ulonglong2 A, B;
        PK2(A.x, x0, x1); PK2(A.y, y0, y1);
        PK2(B.x, z0, z1); PK2(B.y, p20, p21);
        g_pA[b * (Nq / 2) + jp] = A;
        g_pB[b * (Nq / 2) + jp] = B;
    }
}

// ---------------------------------------------------------------------------
// Fused kernel. blockIdx 0..7: FPS producer (R11 structure; SMEM coords
// stored NEGATED so the per-step centroid pack needs no FNEG — operand
// bits into the distance math are unchanged -> bit-exact trajectory).
// blockIdx 8..135: kNN consumer — two 64-center blocks per CTA, 8-way
// point-split + exact u64-key merge + fused aggregation (verbatim R11).
// 136 CTAs co-resident (1/SM) -> spin-waits cannot deadlock.
// ---------------------------------------------------------------------------
#define HSTRIDE 512     // heap column stride (one column per thread)

// hygienic heap insert (reserved _hs_* names; see R8 shadowing post-mortem)
#define HEAP_SIFT(KEY)                                                      \
    {                                                                       \
        const u64p _hs_k = (KEY);                                           \
        u64p _hs_lc = hp[1 * HSTRIDE + tid];                                \
        u64p _hs_rc = hp[2 * HSTRIDE + tid];                                \
        u64p _hs_mc = (_hs_rc > _hs_lc) ? _hs_rc : _hs_lc;                  \
        if (_hs_mc > _hs_k) {                                               \
            hp[0 * HSTRIDE + tid] = _hs_mc;                                 \
            root = _hs_mc;                                                  \
            int _hs_i = (_hs_rc > _hs_lc) ? 2 : 1;                          \
            _Pragma("unroll")                                               \
            for (int _hs_lvl = 1; _hs_lvl < 5; ++_hs_lvl) {                 \
                const int _hs_cn = 2 * _hs_i + 1;                           \
                if (_hs_cn > 31) break;                                     \
                _hs_lc = hp[_hs_cn * HSTRIDE + tid];                        \
                _hs_rc = hp[(_hs_cn + 1) * HSTRIDE + tid];                  \
                _hs_mc = (_hs_rc > _hs_lc) ? _hs_rc : _hs_lc;               \
                if (_hs_mc <= _hs_k) break;                                 \
                hp[_hs_i * HSTRIDE + tid] = _hs_mc;                         \
                _hs_i = (_hs_rc > _hs_lc) ? (_hs_cn + 1) : _hs_cn;          \
            }                                                               \
            hp[_hs_i * HSTRIDE + tid] = _hs_k;                              \
        } else {                                                            \
            hp[0 * HSTRIDE + tid] = _hs_k;                                  \
            root = _hs_k;                                                   \
        }                                                                   \
    }
#define ROOTF_UPDATE()                                                      \
    {                                                                       \
        const unsigned _ru_hi = (unsigned)(root >> 32);                     \
        const unsigned _ru_fb =                                             \
            _ru_hi ^ ((_ru_hi & 0x80000000u) ? 0x80000000u : 0xFFFFFFFFu);  \
        root_f = __uint_as_float(_ru_fb);                                   \
    }
#define MONO(bits) ((bits) ^ ((unsigned)((int)(bits) >> 31) | 0x80000000u))

__global__ void __launch_bounds__(512, 1) fused_kernel(
    const float* __restrict__ coords, const float* __restrict__ feats,
    float* __restrict__ out_coords, float* __restrict__ out_feats)
{
    extern __shared__ char smraw[];
    const int tid = threadIdx.x;

    if (blockIdx.x < Bq) {
        // ============================ FPS role =============================
        float4* sp = (float4*)smraw;       // Nq float4 = 128 KB (NEGATED)
        __shared__ unsigned s_vb[2][16];   // double-buffered per-warp max bits
        __shared__ unsigned s_ib[2][16];   // double-buffered per-warp argmax

        const int b    = blockIdx.x;
        const int w    = tid >> 5, lane = tid & 31;
        const float* cb = coords + (size_t)b * Nq * 3;

        for (int j = tid; j < Nq; j += 512)
            sp[j] = make_float4(-cb[3 * j], -cb[3 * j + 1],
                                -cb[3 * j + 2], 0.0f);
        __syncthreads();

        // pack 16 points/thread; re-negate once at init (-(-x)=x, bit-exact)
        u64p px[8], py[8], pz[8];
        float dist[16];
#pragma unroll
        for (int k = 0; k < 8; ++k) {
            const float4 a = sp[(2 * k) * 512 + tid];
            const float4 c = sp[(2 * k + 1) * 512 + tid];
            PK2(px[k], -a.x, -c.x);
            PK2(py[k], -a.y, -c.y);
            PK2(pz[k], -a.z, -c.z);
            dist[2 * k] = 3.0e38f; dist[2 * k + 1] = 3.0e38f;
        }

        int cur = 0;
        float* ob = out_coords + (size_t)b * Mq * 3;

        for (int step = 0; step < Mq; ++step) {
            const int p = step & 1;
            const float4 c = sp[cur];      // holds (-cx, -cy, -cz)
            if (tid == 0) {
                ob[3 * step + 0] = -c.x;
                ob[3 * step + 1] = -c.y;
                ob[3 * step + 2] = -c.z;
                if ((step & 63) == 63) {  // steps 0..step now final
                    asm volatile("st.release.gpu.global.u32 [%0], %1;"
                                 :: "l"(&g_prog[b]), "r"((unsigned)(step + 1))
                                 : "memory");
                }
            }
            // centroid already negated in smem: pack directly, no FNEG
            u64p ncx, ncy, ncz;
            PK2(ncx, c.x, c.x);
            PK2(ncy, c.y, c.y);
            PK2(ncz, c.z, c.z);

#pragma unroll
            for (int k = 0; k < 8; ++k) {
                u64p dx, dy, dz, xx, yy, zz, ss, dd;
                ADD2(dx, px[k], ncx);      // q.x + (-c.x) == q.x - c.x
                ADD2(dy, py[k], ncy);
                ADD2(dz, pz[k], ncz);
                MUL2(xx, dx, dx);
                MUL2(yy, dy, dy);
                MUL2(zz, dz, dz);
                ADD2(ss, xx, yy);
                ADD2(dd, ss, zz);
                float d0, d1; UPK2(d0, d1, dd);
                dist[2 * k]     = fminf(dist[2 * k], d0);
                dist[2 * k + 1] = fminf(dist[2 * k + 1], d1);
            }
            // per-thread max (tree)
            float bv = dist[0];
#pragma unroll
            for (int i = 1; i < 16; ++i) bv = fmaxf(bv, dist[i]);

            // issue the value redux FIRST so its latency shadows the scan
            const unsigned bb = __float_as_uint(bv);
            const unsigned wm = redux_max_u32(bb);

            // parallel lowest-matching-slot recovery (pair test + min tree)
            int ck[8];
#pragma unroll
            for (int k = 0; k < 8; ++k)
                ck[k] = (dist[2 * k] == bv) ? (2 * k)
                        : ((dist[2 * k + 1] == bv) ? (2 * k + 1) : 64);
#pragma unroll
            for (int o = 4; o > 0; o >>= 1)
#pragma unroll
                for (int k = 0; k < o; ++k)
                    ck[k] = min(ck[k], ck[k + o]);
            const int bi = ck[0] * 512 + tid;

            const unsigned wbi =
                redux_min_u32((bb == wm) ? (unsigned)bi : 0x7fffffffu);
            if (lane == 0) { s_vb[p][w] = wm; s_ib[p][w] = wbi; }
            __syncthreads();

            // stage2: every warp redundantly reduces the 16 candidates
            const unsigned v2 = (lane < 16) ? s_vb[p][lane] : 0u;
            const unsigned i2 = (lane < 16) ? s_ib[p][lane] : 0x7fffffffu;
            const unsigned m2 = redux_max_u32(v2);
            cur = (int)redux_min_u32(
                (v2 == m2 && lane < 16) ? i2 : 0x7fffffffu);
        }
        if (tid == 0)
            asm volatile("st.release.gpu.global.u32 [%0], %1;"
                         :: "l"(&g_prog[b]), "r"((unsigned)Mq) : "memory");
        return;
    }

    // ======================= kNN + aggregation role =======================
    // CTA handles two 64-center blocks of batch b: blk = xb and xb+16.
    u64p* hp = (u64p*)smraw;               // 33 x 512 u64 = 132 KB
    const int cta = blockIdx.x - Bq;
    const int b   = cta & 7;               // batch
    const int xb  = cta >> 3;              // 0..15
    const int t   = tid & 63;              // center slot (0..63)
    const int g   = tid >> 6;              // point split (0..7)

    const u64p INIT_KEY = 0xFF800000FFFFFFFFull;
    const ulonglong2* pA = g_pA + (size_t)b * (Nq / 2);
    const ulonglong2* pB = g_pB + (size_t)b * (Nq / 2);

#pragma unroll 1
    for (int item = 0; item < 2; ++item) {
        const int blk = xb + item * 16;    // 64-center block (0..31)
        __syncthreads();                   // prev item's agg reads done

        // heap init: 32 real nodes -> +inf keys; slot 32 = 0-sentinel
#pragma unroll
        for (int n = 0; n < 32; ++n) hp[n * HSTRIDE + tid] = INIT_KEY;
        hp[32 * HSTRIDE + tid] = 0ull;
        __syncthreads();

        // wait for FPS progress (centers [0, (blk+1)*64) final)
        const unsigned need = (unsigned)((blk + 1) * 64);
        if (tid == 0) {
            unsigned v;
            do {
                asm volatile("ld.acquire.gpu.global.u32 %0, [%1];"
                             : "=r"(v) : "l"(&g_prog[b]) : "memory");
                if (v >= need) break;
                __nanosleep(256);
            } while (true);
        }
        __syncthreads();
        {   // per-thread acquire (counter monotone -> sees >= need)
            unsigned v;
            asm volatile("ld.acquire.gpu.global.u32 %0, [%1];"
                         : "=r"(v) : "l"(&g_prog[b]) : "memory");
            (void)v;
        }

        const int m = blk * 64 + t;        // center index within batch
        const float* cc = out_coords + ((size_t)b * Mq + m) * 3;
        const float cx = cc[0], cy = cc[1], cz = cc[2];
        const float c2 = __fadd_rn(
            __fadd_rn(__fmul_rn(cx, cx), __fmul_rn(cy, cy)),
            __fmul_rn(cz, cz));
        u64p vcx, vcy, vcz, vc2, vn2, vz0;
        PK2(vcx, cx, cx); PK2(vcy, cy, cy); PK2(vcz, cz, cz);
        PK2(vc2, c2, c2); PK2(vn2, -2.0f, -2.0f); PK2(vz0, 0.0f, 0.0f);

        u64p  root   = INIT_KEY;
        float root_f = __uint_as_float(0x7F800000u);   // +inf

        // scan this 1/8 split of the points (bit-exact distance math)
        const int jp0 = g * (Nq / 16), jp1 = jp0 + (Nq / 16);
#pragma unroll 4
        for (int jp = jp0; jp < jp1; ++jp) {
            const ulonglong2 A = pA[jp];
            const ulonglong2 B = pB[jp];
            u64p tt, dotv, s2, d2v;
            MUL2(tt, A.x, vcx);
            FMA2(tt, A.y, vcy, tt);
            FMA2(dotv, B.x, vcz, tt);
            ADD2(s2, vc2, B.y);
            FMA2(d2v, dotv, vn2, s2);
            ADD2(d2v, d2v, vz0);       // -0 -> +0 (value otherwise exact)
            float d0, d1; UPK2(d0, d1, d2v);
            if (d0 < root_f) {
                u64p k0; const unsigned m0 = MONO(__float_as_uint(d0));
                asm("mov.b64 %0, {%1, %2};" : "=l"(k0)
                    : "r"((unsigned)(2 * jp)), "r"(m0));
                HEAP_SIFT(k0) ROOTF_UPDATE()
            }
            if (d1 < root_f) {
                u64p k1; const unsigned m1 = MONO(__float_as_uint(d1));
                asm("mov.b64 %0, {%1, %2};" : "=l"(k1)
                    : "r"((unsigned)(2 * jp + 1)), "r"(m1));
                HEAP_SIFT(k1) ROOTF_UPDATE()
            }
        }
        __syncthreads();

        // merge: thread t (<64) folds the 7 foreign partial heaps into its
        // own column. u64 key order == (value, index) stable top_k rule.
        if (tid < 64) {
#pragma unroll
            for (int g2 = 1; g2 < 8; ++g2) {
                const int col = t + 64 * g2;
#pragma unroll
                for (int n = 0; n < 32; ++n) {
                    const u64p fkey = hp[n * HSTRIDE + col];
                    if (fkey < root) HEAP_SIFT(fkey)
                }
            }
        }
        __syncthreads();

        // fused aggregation: warp w handles centers w*4..w*4+3; lane =
        // channel quad. Indices from heap low words (ascending slots).
        const int w = tid >> 5, lane = tid & 31;
        const unsigned* hlo = (const unsigned*)hp;
        const float4* fb4 = (const float4*)(feats + (size_t)b * Nq * Cq);
#pragma unroll
        for (int c4 = 0; c4 < 4; ++c4) {
            const int c  = w * 4 + c4;         // center slot 0..63
            const int mm = blk * 64 + c;
            float ax = 0.f, ay = 0.f, az = 0.f, aw = 0.f;
#pragma unroll
            for (int s = 0; s < Kq; ++s) {
                const unsigned idx = hlo[(s * HSTRIDE + c) * 2];
                const float4 v = fb4[(size_t)idx * 32 + lane];
                ax += v.x; ay += v.y; az += v.z; aw += v.w;
            }
            float4 r;
            r.x = ax * 0.03125f; r.y = ay * 0.03125f;
            r.z = az * 0.03125f; r.w = aw * 0.03125f;
            ((float4*)out_feats)[((size_t)b * Mq + mm) * 32 + lane] = r;
        }
    }
}

// ---------------------------------------------------------------------------
extern "C" void kernel_launch(void* const* d_in, const int* in_sizes, int n_in,
                              void* d_out, int out_size)
{
    const float* coords = (const float*)d_in[0];  // (8, 8192, 3) f32
    const float* feats  = (const float*)d_in[1];  // (8, 8192, 128) f32
    float* out        = (float*)d_out;
    float* out_coords = out;                       // (8, 2048, 3)
    float* out_feats  = out + (size_t)Bq * Mq * 3; // (8, 2048, 128)

    const int fused_smem = 33 * HSTRIDE * 8;       // 135,168 B (>= 128 KB FPS)

    cudaFuncSetAttribute(fused_kernel, cudaFuncAttributeMaxDynamicSharedMemorySize,
                         fused_smem);

    pack_kernel<<<Bq * 8, 512>>>(coords);
    fused_kernel<<<Bq + Bq * 16, 512, fused_smem>>>(coords, feats,
                                                    out_coords, out_feats);
}